// round 16
// baseline (speedup 1.0000x reference)
#include <cuda_runtime.h>
#include <cuda_fp16.h>
#include <cstdint>
#include <math.h>

// ---------------- problem constants ----------------
#define Dm     1024
#define Lnum   2
#define Hh     16
#define DHh    64
#define INNERd 1024
#define MLPd   4096
#define Ee     8
#define Bb     4
#define Nn     1024
#define Tt     (Bb*Nn)
#define NEXP   (Ee-1)

// weight pack offsets (elements, per layer)
#define SZ1M   (1024L*1024L)
#define OFF_QKV 0L
#define OFF_WO  (OFF_QKV + 3072L*1024L)
#define OFF_WB0 (OFF_WO  + SZ1M)
#define OFF_WB1 (OFF_WB0 + SZ1M)
#define OFF_WEP (OFF_WB1 + SZ1M)
#define OFF_WEA (OFF_WEP + 7L*SZ1M)
#define OFF_WA1 (OFF_WEA + 7L*SZ1M)
#define OFF_WA2 (OFF_WA1 + 4096L*1024L)
#define PER_L   (OFF_WA2 + 4096L*1024L)

// ---------------- scratch (device globals) ----------------
__device__ float g_x[Tt*Dm];
__device__ __half g_pa[(size_t)2*NEXP*Tt*Dm];
__device__ float g_w[Lnum*Tt*Ee];
__device__ __half g_whi[2L*PER_L];
__device__ __half g_wlo[2L*PER_L];
__device__ __half g_ahi[(size_t)Tt*Dm];
__device__ __half g_alo[(size_t)Tt*Dm];
__device__ __half g_mhi[(size_t)Tt*MLPd];
__device__ __half g_mlo[(size_t)Tt*MLPd];
__device__ __half g_qkvh[(size_t)Tt*3*INNERd];
__device__ __half g_vt[(size_t)Bb*Hh*DHh*Nn];
__device__ int g_cnt[NEXP];
__device__ int g_eidx[(size_t)NEXP*Tt];

__device__ __forceinline__ float gelu_f(float v) {
    return 0.5f * v * (1.0f + erff(v * 0.7071067811865475f));
}

__device__ __forceinline__ uint32_t smem_u32(const void* p) {
    uint32_t a;
    asm("{ .reg .u64 t; cvta.to.shared.u64 t, %1; cvt.u32.u64 %0, t; }"
        : "=r"(a) : "l"(p));
    return a;
}
__device__ __forceinline__ void ldmx4(uint32_t* r, uint32_t addr) {
    asm volatile("ldmatrix.sync.aligned.m8n8.x4.shared.b16 {%0,%1,%2,%3}, [%4];"
        : "=r"(r[0]), "=r"(r[1]), "=r"(r[2]), "=r"(r[3]) : "r"(addr));
}
__device__ __forceinline__ void ldmx2(uint32_t* r, uint32_t addr) {
    asm volatile("ldmatrix.sync.aligned.m8n8.x2.shared.b16 {%0,%1}, [%2];"
        : "=r"(r[0]), "=r"(r[1]) : "r"(addr));
}
__device__ __forceinline__ void mma16816(float* d, const uint32_t* a, const uint32_t* b) {
    asm volatile("mma.sync.aligned.m16n8k16.row.col.f32.f16.f16.f32 "
        "{%0,%1,%2,%3}, {%4,%5,%6,%7}, {%8,%9}, {%0,%1,%2,%3};"
        : "+f"(d[0]), "+f"(d[1]), "+f"(d[2]), "+f"(d[3])
        : "r"(a[0]), "r"(a[1]), "r"(a[2]), "r"(a[3]), "r"(b[0]), "r"(b[1]));
}

// ================= split HMMA GEMM (2 or 3 terms), 2-stage, 2 CTAs/SM =================
#define BM 128
#define BN 128
#define BK 32
#define LDT 40
#define TILE_B (128*LDT*2)
#define ST_AHI 0
#define ST_ALO (1*TILE_B)
#define ST_BHI (2*TILE_B)
#define ST_BLO (3*TILE_B)
#define STAGE_B (4*TILE_B)
#define SMEM_MM (2*STAGE_B)

#define GEMM_PHASE(base, ph)                                                      \
    do {                                                                          \
        uint32_t bhi[4][2], blo[4][2], af[4][4];                                  \
        _Pragma("unroll")                                                         \
        for (int nt = 0; nt < 4; nt++) {                                          \
            int rr = wn * 32 + nt * 8 + (lane & 7);                               \
            uint32_t co = (uint32_t)(rr * LDT + (ph) * 16 + ((lane >> 3) & 1) * 8) * 2; \
            ldmx2(bhi[nt], (base) + ST_BHI + co);                                 \
            ldmx2(blo[nt], (base) + ST_BLO + co);                                 \
        }                                                                         \
        _Pragma("unroll")                                                         \
        for (int mt = 0; mt < 4; mt++) {                                          \
            int rr = wm * 64 + mt * 16 + (lane & 15);                             \
            uint32_t co = (uint32_t)(rr * LDT + (ph) * 16 + (lane >> 4) * 8) * 2; \
            ldmx4(af[mt], (base) + ST_AHI + co);                                  \
        }                                                                         \
        _Pragma("unroll")                                                         \
        for (int mt = 0; mt < 4; mt++)                                            \
            _Pragma("unroll")                                                     \
            for (int nt = 0; nt < 4; nt++) {                                      \
                mma16816(acc[mt][nt], af[mt], bhi[nt]);                           \
                mma16816(acc[mt][nt], af[mt], blo[nt]);                           \
            }                                                                     \
        if (terms == 3) {                                                         \
            _Pragma("unroll")                                                     \
            for (int mt = 0; mt < 4; mt++) {                                      \
                int rr = wm * 64 + mt * 16 + (lane & 15);                         \
                uint32_t co = (uint32_t)(rr * LDT + (ph) * 16 + (lane >> 4) * 8) * 2; \
                ldmx4(af[mt], (base) + ST_ALO + co);                              \
            }                                                                     \
            _Pragma("unroll")                                                     \
            for (int mt = 0; mt < 4; mt++)                                        \
                _Pragma("unroll")                                                 \
                for (int nt = 0; nt < 4; nt++)                                    \
                    mma16816(acc[mt][nt], af[mt], bhi[nt]);                       \
        }                                                                         \
    } while (0)

__global__ __launch_bounds__(256, 2) void mma_gemm_kernel(
    const __half* __restrict__ Ahi, const __half* __restrict__ Alo,
    const __half* __restrict__ Bhi, const __half* __restrict__ Blo,
    const float* __restrict__ bias, const float* __restrict__ resid,
    float* __restrict__ C, __half* __restrict__ Chi, __half* __restrict__ Clo,
    int M, int N, int K, long sB, long sC, int act,
    int hasBias, int hasRes, int wantF32, int wantHi, int wantLo, int terms)
{
    extern __shared__ char smem[];
    uint32_t sb = smem_u32(smem);
    const int tid = threadIdx.x;
    const int wid = tid >> 5;
    const int lane = tid & 31;
    const long z = blockIdx.z;
    Bhi += z * sB;
    Blo += z * sB;
    if (wantF32) C += z * sC;
    if (wantHi) Chi += z * sC;
    if (wantLo) Clo += z * sC;
    const float* res = hasRes ? (resid + z * sC) : nullptr;
    const int row0 = blockIdx.y * BM;
    const int col0 = blockIdx.x * BN;
    const int wm = wid & 1;
    const int wn = wid >> 1;

    float acc[4][4][4];
#pragma unroll
    for (int a = 0; a < 4; a++)
#pragma unroll
        for (int b = 0; b < 4; b++)
#pragma unroll
            for (int c = 0; c < 4; c++) acc[a][b][c] = 0.f;

    const int nc = K / BK;

    auto load_stage = [&](int s, int kt) {
        uint32_t base = sb + s * STAGE_B;
#pragma unroll
        for (int i = 0; i < 8; i++) {
            int idx = i * 256 + tid;
            int mat = idx >> 9;
            if (terms == 2 && mat == 1) continue;
            int rem = idx & 511;
            int r = rem >> 2, c = rem & 3;
            uint32_t sa = base + mat * TILE_B + (uint32_t)(r * LDT + c * 8) * 2;
            const __half* gp;
            if (mat == 0)      gp = Ahi + (long)(row0 + r) * K + kt + c * 8;
            else if (mat == 1) gp = Alo + (long)(row0 + r) * K + kt + c * 8;
            else if (mat == 2) gp = Bhi + (long)(col0 + r) * K + kt + c * 8;
            else               gp = Blo + (long)(col0 + r) * K + kt + c * 8;
            asm volatile("cp.async.cg.shared.global [%0], [%1], 16;"
                         :: "r"(sa), "l"(gp));
        }
        asm volatile("cp.async.commit_group;");
    };

    load_stage(0, 0);

    for (int c = 0; c < nc; c++) {
        int s = c & 1;
        if (c + 1 < nc) {
            load_stage(s ^ 1, (c + 1) * BK);
            asm volatile("cp.async.wait_group 1;");
        } else {
            asm volatile("cp.async.wait_group 0;");
        }
        __syncthreads();
        uint32_t base = sb + s * STAGE_B;
        GEMM_PHASE(base, 0);
        GEMM_PHASE(base, 1);
        __syncthreads();
    }

#pragma unroll
    for (int mt = 0; mt < 4; mt++) {
#pragma unroll
        for (int nt = 0; nt < 4; nt++) {
            int rb = row0 + wm * 64 + mt * 16 + (lane >> 2);
            int cc = col0 + wn * 32 + nt * 8 + (lane & 3) * 2;
            float b0 = 0.f, b1 = 0.f;
            if (hasBias) { b0 = bias[cc]; b1 = bias[cc + 1]; }
#pragma unroll
            for (int hf = 0; hf < 2; hf++) {
                int rr = rb + hf * 8;
                float v0 = acc[mt][nt][hf * 2] + b0;
                float v1 = acc[mt][nt][hf * 2 + 1] + b1;
                if (act == 1) { v0 = gelu_f(v0); v1 = gelu_f(v1); }
                if (hasRes) {
                    v0 += res[(long)rr * N + cc];
                    v1 += res[(long)rr * N + cc + 1];
                }
                long o = (long)rr * N + cc;
                if (wantF32) *(float2*)&C[o] = make_float2(v0, v1);
                if (wantHi) {
                    __half h0 = __float2half_rn(v0), h1 = __float2half_rn(v1);
                    *(__half2*)&Chi[o] = __halves2half2(h0, h1);
                    if (wantLo) {
                        __half l0 = __float2half_rn(v0 - __half2float(h0));
                        __half l1 = __float2half_rn(v1 - __half2float(h1));
                        *(__half2*)&Clo[o] = __halves2half2(l0, l1);
                    }
                }
            }
        }
    }
}

// ================= token-gathered sparse expert GEMM (fp16 output) =================
__global__ __launch_bounds__(256, 2) void mma_gather_kernel(
    const __half* __restrict__ Ahi, const __half* __restrict__ Alo,
    const __half* __restrict__ Whi, const __half* __restrict__ Wlo,
    __half* __restrict__ PA,
    const int* __restrict__ cnt, const int* __restrict__ eidx, int terms)
{
    const int z = blockIdx.z;
    const int e = z % NEXP;
    const int n = cnt[e];
    const int row0 = blockIdx.y * BM;
    if (row0 >= n) return;

    extern __shared__ char smem[];
    uint32_t sb = smem_u32(smem);
    __shared__ int sidx[BM];
    const int tid = threadIdx.x;
    const int wid = tid >> 5;
    const int lane = tid & 31;
    const __half* Bhi = Whi + (long)z * SZ1M;
    const __half* Blo = Wlo + (long)z * SZ1M;
    __half* C = PA + (long)z * Tt * Dm;
    const int col0 = blockIdx.x * BN;
    const int wm = wid & 1;
    const int wn = wid >> 1;
    const int K = Dm;

    if (tid < BM) {
        int rr = row0 + tid;
        sidx[tid] = eidx[(long)e * Tt + (rr < n ? rr : n - 1)];
    }
    __syncthreads();

    float acc[4][4][4];
#pragma unroll
    for (int a = 0; a < 4; a++)
#pragma unroll
        for (int b = 0; b < 4; b++)
#pragma unroll
            for (int c = 0; c < 4; c++) acc[a][b][c] = 0.f;

    const int nc = K / BK;

    auto load_stage = [&](int s, int kt) {
        uint32_t base = sb + s * STAGE_B;
#pragma unroll
        for (int i = 0; i < 8; i++) {
            int idx = i * 256 + tid;
            int mat = idx >> 9;
            if (terms == 2 && mat == 1) continue;
            int rem = idx & 511;
            int r = rem >> 2, c = rem & 3;
            uint32_t sa = base + mat * TILE_B + (uint32_t)(r * LDT + c * 8) * 2;
            const __half* gp;
            if (mat == 0)      gp = Ahi + (long)sidx[r] * K + kt + c * 8;
            else if (mat == 1) gp = Alo + (long)sidx[r] * K + kt + c * 8;
            else if (mat == 2) gp = Bhi + (long)(col0 + r) * K + kt + c * 8;
            else               gp = Blo + (long)(col0 + r) * K + kt + c * 8;
            asm volatile("cp.async.cg.shared.global [%0], [%1], 16;"
                         :: "r"(sa), "l"(gp));
        }
        asm volatile("cp.async.commit_group;");
    };

    load_stage(0, 0);

    for (int c = 0; c < nc; c++) {
        int s = c & 1;
        if (c + 1 < nc) {
            load_stage(s ^ 1, (c + 1) * BK);
            asm volatile("cp.async.wait_group 1;");
        } else {
            asm volatile("cp.async.wait_group 0;");
        }
        __syncthreads();
        uint32_t base = sb + s * STAGE_B;
        GEMM_PHASE(base, 0);
        GEMM_PHASE(base, 1);
        __syncthreads();
    }

#pragma unroll
    for (int mt = 0; mt < 4; mt++) {
#pragma unroll
        for (int nt = 0; nt < 4; nt++) {
            int lr = wm * 64 + mt * 16 + (lane >> 2);
            int cc = col0 + wn * 32 + nt * 8 + (lane & 3) * 2;
#pragma unroll
            for (int hf = 0; hf < 2; hf++) {
                int lrr = lr + hf * 8;
                if (row0 + lrr < n) {
                    long o = (long)sidx[lrr] * Dm + cc;
                    *(__half2*)&C[o] = __halves2half2(
                        __float2half_rn(acc[mt][nt][hf * 2]),
                        __float2half_rn(acc[mt][nt][hf * 2 + 1]));
                }
            }
        }
    }
}

// ================= fused flash attention =================
#define FLD 72
#define F_QOFF 0
#define F_SOFF (128*FLD*2)
#define F_KOFF (2*128*FLD*2)
#define F_KT  (64*FLD*2)
#define F_VOFF (F_KOFF + 2*F_KT)
#define SMEM_F (F_VOFF + 2*F_KT)

__global__ __launch_bounds__(256, 2) void flash_kernel(
    const __half* __restrict__ qkvh, const __half* __restrict__ vt,
    __half* __restrict__ Ohi, __half* __restrict__ Olo)
{
    extern __shared__ char smem[];
    __shared__ float rs[128][2];
    uint32_t sb = smem_u32(smem);
    const int tid = threadIdx.x;
    const int wid = tid >> 5;
    const int lane = tid & 31;
    const int z = blockIdx.y;
    const int b = z >> 4, h = z & 15;
    const int row0 = blockIdx.x * 128;
    const int wm = wid & 1;
    const int wn = wid >> 1;

    const __half* Qg = qkvh + (long)(b * Nn) * 3072 + h * 64;
    const __half* Kg = Qg + INNERd;
    const __half* Vg = vt + (long)z * DHh * Nn;

#pragma unroll
    for (int i = 0; i < 4; i++) {
        int idx = i * 256 + tid;
        int r = idx >> 3, c = idx & 7;
        uint32_t sa = sb + F_QOFF + (uint32_t)(r * FLD + c * 8) * 2;
        const __half* gp = Qg + (long)(row0 + r) * 3072 + c * 8;
        asm volatile("cp.async.cg.shared.global [%0], [%1], 16;"
                     :: "r"(sa), "l"(gp));
    }
    asm volatile("cp.async.commit_group;");

    auto load_kv = [&](int s, int kt) {
#pragma unroll
        for (int i = 0; i < 2; i++) {
            int idx = i * 256 + tid;
            int r = idx >> 3, c = idx & 7;
            uint32_t sa = sb + F_KOFF + s * F_KT + (uint32_t)(r * FLD + c * 8) * 2;
            const __half* gp = Kg + (long)(kt + r) * 3072 + c * 8;
            asm volatile("cp.async.cg.shared.global [%0], [%1], 16;"
                         :: "r"(sa), "l"(gp));
        }
#pragma unroll
        for (int i = 0; i < 2; i++) {
            int idx = i * 256 + tid;
            int r = idx >> 3, c = idx & 7;
            uint32_t sa = sb + F_VOFF + s * F_KT + (uint32_t)(r * FLD + c * 8) * 2;
            const __half* gp = Vg + (long)r * Nn + kt + c * 8;
            asm volatile("cp.async.cg.shared.global [%0], [%1], 16;"
                         :: "r"(sa), "l"(gp));
        }
        asm volatile("cp.async.commit_group;");
    };

    load_kv(0, 0);
    asm volatile("cp.async.wait_group 0;");
    __syncthreads();

    float oacc[4][2][4];
#pragma unroll
    for (int a = 0; a < 4; a++)
#pragma unroll
        for (int bb = 0; bb < 2; bb++)
#pragma unroll
            for (int c = 0; c < 4; c++) oacc[a][bb][c] = 0.f;
    float fsum = 0.f;

    const int nt_tiles = Nn / 64;
    for (int t = 0; t < nt_tiles; t++) {
        int s = t & 1;
        if (t + 1 < nt_tiles) load_kv(s ^ 1, (t + 1) * 64);

        float sacc[4][2][4];
#pragma unroll
        for (int a = 0; a < 4; a++)
#pragma unroll
            for (int bb = 0; bb < 2; bb++)
#pragma unroll
                for (int c = 0; c < 4; c++) sacc[a][bb][c] = 0.f;
#pragma unroll
        for (int ph = 0; ph < 4; ph++) {
            uint32_t af[4][4], bf[2][2];
#pragma unroll
            for (int mt = 0; mt < 4; mt++) {
                int rr = wm * 64 + mt * 16 + (lane & 15);
                uint32_t co = (uint32_t)(rr * FLD + ph * 16 + (lane >> 4) * 8) * 2;
                ldmx4(af[mt], sb + F_QOFF + co);
            }
#pragma unroll
            for (int nt = 0; nt < 2; nt++) {
                int rr = wn * 16 + nt * 8 + (lane & 7);
                uint32_t co = (uint32_t)(rr * FLD + ph * 16 + ((lane >> 3) & 1) * 8) * 2;
                ldmx2(bf[nt], sb + F_KOFF + s * F_KT + co);
            }
#pragma unroll
            for (int mt = 0; mt < 4; mt++)
#pragma unroll
                for (int nt = 0; nt < 2; nt++)
                    mma16816(sacc[mt][nt], af[mt], bf[nt]);
        }
#pragma unroll
        for (int mt = 0; mt < 4; mt++)
#pragma unroll
            for (int nt = 0; nt < 2; nt++)
#pragma unroll
                for (int hf = 0; hf < 2; hf++) {
                    int row = wm * 64 + mt * 16 + (lane >> 2) + hf * 8;
                    int col = wn * 16 + nt * 8 + (lane & 3) * 2;
                    float v0 = expf(sacc[mt][nt][hf * 2] * 0.125f);
                    float v1 = expf(sacc[mt][nt][hf * 2 + 1] * 0.125f);
                    *(__half2*)(smem + F_SOFF + (size_t)(row * FLD + col) * 2) =
                        __halves2half2(__float2half_rn(v0), __float2half_rn(v1));
                }
        __syncthreads();

        {
            int r = tid & 127, hf2 = tid >> 7;
            const __half2* ap = (const __half2*)(smem + F_SOFF
                                                 + (size_t)(r * FLD + hf2 * 32) * 2);
            float lsum = 0.f;
#pragma unroll
            for (int j = 0; j < 16; j++) {
                float2 f = __half22float2(ap[j]);
                lsum += f.x + f.y;
            }
            fsum += lsum;
        }

#pragma unroll
        for (int ph = 0; ph < 4; ph++) {
            uint32_t af[4][4], bf[2][2];
#pragma unroll
            for (int mt = 0; mt < 4; mt++) {
                int rr = wm * 64 + mt * 16 + (lane & 15);
                uint32_t co = (uint32_t)(rr * FLD + ph * 16 + (lane >> 4) * 8) * 2;
                ldmx4(af[mt], sb + F_SOFF + co);
            }
#pragma unroll
            for (int nt = 0; nt < 2; nt++) {
                int rr = wn * 16 + nt * 8 + (lane & 7);
                uint32_t co = (uint32_t)(rr * FLD + ph * 16 + ((lane >> 3) & 1) * 8) * 2;
                ldmx2(bf[nt], sb + F_VOFF + s * F_KT + co);
            }
#pragma unroll
            for (int mt = 0; mt < 4; mt++)
#pragma unroll
                for (int nt = 0; nt < 2; nt++)
                    mma16816(oacc[mt][nt], af[mt], bf[nt]);
        }
        asm volatile("cp.async.wait_group 0;");
        __syncthreads();
    }

    rs[tid & 127][tid >> 7] = fsum;
    __syncthreads();

#pragma unroll
    for (int mt = 0; mt < 4; mt++)
#pragma unroll
        for (int nt = 0; nt < 2; nt++)
#pragma unroll
            for (int hf = 0; hf < 2; hf++) {
                int lr = wm * 64 + mt * 16 + (lane >> 2) + hf * 8;
                int cc = wn * 16 + nt * 8 + (lane & 3) * 2;
                float inv = 1.f / (rs[lr][0] + rs[lr][1]);
                float v0 = oacc[mt][nt][hf * 2] * inv;
                float v1 = oacc[mt][nt][hf * 2 + 1] * inv;
                long o = (long)(b * Nn + row0 + lr) * INNERd + h * 64 + cc;
                __half h0 = __float2half_rn(v0), h1 = __float2half_rn(v1);
                *(__half2*)&Ohi[o] = __halves2half2(h0, h1);
                __half l0 = __float2half_rn(v0 - __half2float(h0));
                __half l1 = __float2half_rn(v1 - __half2float(h1));
                *(__half2*)&Olo[o] = __halves2half2(l0, l1);
            }
}

// ---------------- V transpose ----------------
__global__ __launch_bounds__(256) void vtrans_kernel(const __half* __restrict__ qkvh,
                                                     __half* __restrict__ vt)
{
    __shared__ __half t[32][33];
    int z = blockIdx.z, b = z >> 4, h = z & 15;
    int k0 = blockIdx.x * 32, d0 = blockIdx.y * 32;
    int tx = threadIdx.x & 31, ty = threadIdx.x >> 5;
#pragma unroll
    for (int i = 0; i < 4; i++) {
        int k = k0 + ty + i * 8;
        t[ty + i * 8][tx] = qkvh[(long)(b * Nn + k) * 3072 + 2048 + h * 64 + d0 + tx];
    }
    __syncthreads();
#pragma unroll
    for (int i = 0; i < 4; i++) {
        int d = d0 + ty + i * 8;
        vt[((long)z * 64 + d) * Nn + k0 + tx] = t[tx][ty + i * 8];
    }
}

// ---------------- weight transpose + fp16 split core (64 K-rows x 128 N-cols) ----------------
__device__ __forceinline__ void wsplit_tile(const float* __restrict__ Wz,
                                            __half* __restrict__ hi,
                                            __half* __restrict__ lo,
                                            long ob, int K, int N,
                                            int k0, int n0, int tid)
{
    __shared__ float tile[64][129];
    // reads: 64 rows x 32 float4 = 2048 -> 8/thread
#pragma unroll
    for (int i = 0; i < 8; i++) {
        int idx = i * 256 + tid;
        int r = idx >> 5, c4 = idx & 31;
        float4 v = *(const float4*)(Wz + (long)(k0 + r) * N + n0 + c4 * 4);
        tile[r][c4 * 4 + 0] = v.x; tile[r][c4 * 4 + 1] = v.y;
        tile[r][c4 * 4 + 2] = v.z; tile[r][c4 * 4 + 3] = v.w;
    }
    __syncthreads();
    // writes: 128 n-rows x 8 kg = 1024 -> 4/thread
#pragma unroll
    for (int i = 0; i < 4; i++) {
        int idx = i * 256 + tid;
        int nn = idx >> 3, kg = idx & 7;
        __half hbuf[8], lbuf[8];
#pragma unroll
        for (int j = 0; j < 8; j++) {
            float v = tile[kg * 8 + j][nn];
            __half h = __float2half_rn(v);
            hbuf[j] = h;
            lbuf[j] = __float2half_rn(v - __half2float(h));
        }
        long o = ob + (long)(n0 + nn) * K + k0 + kg * 8;
        *(uint4*)(hi + o) = *(uint4*)hbuf;
        *(uint4*)(lo + o) = *(uint4*)lbuf;
    }
}

__global__ __launch_bounds__(256) void wsplit_kernel(
    const float* __restrict__ W, __half* __restrict__ hi, __half* __restrict__ lo,
    int K, int N, long inStride, long outStride)
{
    wsplit_tile(W + blockIdx.z * inStride, hi, lo, (long)blockIdx.z * outStride,
                K, N, blockIdx.y * 64, blockIdx.x * 128, threadIdx.x);
}

__global__ __launch_bounds__(256) void wsplit3_kernel(
    const float* __restrict__ W0, const float* __restrict__ W1,
    const float* __restrict__ W2,
    __half* __restrict__ hi, __half* __restrict__ lo)
{
    int z = blockIdx.z;
    int t = z >> 1, l = z & 1;
    const float* src = (t == 0 ? W0 : (t == 1 ? W1 : W2)) + (long)l * SZ1M;
    long off = (t == 0 ? OFF_WO : (t == 1 ? OFF_WB0 : OFF_WB1)) + (long)l * PER_L;
    wsplit_tile(src, hi, lo, off, 1024, 1024,
                blockIdx.y * 64, blockIdx.x * 128, threadIdx.x);
}

__global__ __launch_bounds__(256) void wsplitE_kernel(
    const float* __restrict__ Wp, const float* __restrict__ Wa,
    __half* __restrict__ hi, __half* __restrict__ lo)
{
    int z = blockIdx.z;
    int l = z / 14, s = z % 14;
    const float* src = (s < 7 ? Wp + (long)l * 7 * SZ1M + (long)s * SZ1M
                              : Wa + (long)l * 7 * SZ1M + (long)(s - 7) * SZ1M);
    long off = (long)l * PER_L + OFF_WEP + (long)s * SZ1M;
    wsplit_tile(src, hi, lo, off, 1024, 1024,
                blockIdx.y * 64, blockIdx.x * 128, threadIdx.x);
}

// ---------------- LayerNorm -> fp16 hi(/lo) ----------------
__global__ __launch_bounds__(256) void ln_split_kernel(
    const float* __restrict__ x, const float* __restrict__ g,
    const float* __restrict__ bta,
    __half* __restrict__ hi, __half* __restrict__ lo, int wantLo)
{
    int t = blockIdx.x, tid = threadIdx.x;
    const float* xp = x + (long)t * Dm;
    __shared__ float r1[256], r2[256];

    float v[4], s = 0.f, s2 = 0.f;
#pragma unroll
    for (int i = 0; i < 4; i++) { v[i] = xp[tid + i * 256]; s += v[i]; s2 += v[i] * v[i]; }
    r1[tid] = s; r2[tid] = s2; __syncthreads();
    for (int st = 128; st > 0; st >>= 1) {
        if (tid < st) { r1[tid] += r1[tid + st]; r2[tid] += r2[tid + st]; }
        __syncthreads();
    }
    float mean = r1[0] * (1.f / Dm);
    float var = r2[0] * (1.f / Dm) - mean * mean;
    float rstd = rsqrtf(var + 1e-5f);
#pragma unroll
    for (int i = 0; i < 4; i++) {
        int d = tid + i * 256;
        float y = (v[i] - mean) * rstd * g[d] + bta[d];
        __half h = __float2half_rn(y);
        hi[(long)t * Dm + d] = h;
        if (wantLo) lo[(long)t * Dm + d] = __float2half_rn(y - __half2float(h));
    }
}

// ---------------- reset expert counters ----------------
__global__ void reset_cnt_kernel(int* cnt)
{
    if (threadIdx.x < NEXP) cnt[threadIdx.x] = 0;
}

// ---------------- router (+ expert token gather) ----------------
__global__ __launch_bounds__(128) void router_kernel(const float* __restrict__ x,
                                                     const float* __restrict__ Wr,
                                                     const float* __restrict__ br,
                                                     float* __restrict__ wout,
                                                     int* __restrict__ cnt,
                                                     int* __restrict__ eidx)
{
    int t = blockIdx.x, tid = threadIdx.x;
    __shared__ float part[128][Ee];
    float acc[Ee];
#pragma unroll
    for (int e = 0; e < Ee; e++) acc[e] = 0.f;
    const float* xp = x + (long)t * Dm;
    for (int d = tid; d < Dm; d += 128) {
        float xv = xp[d];
        const float* wrow = Wr + (long)d * Ee;
#pragma unroll
        for (int e = 0; e < Ee; e++) acc[e] += xv * wrow[e];
    }
#pragma unroll
    for (int e = 0; e < Ee; e++) part[tid][e] = acc[e];
    __syncthreads();
    for (int st = 64; st > 0; st >>= 1) {
        if (tid < st)
#pragma unroll
            for (int e = 0; e < Ee; e++) part[tid][e] += part[tid + st][e];
        __syncthreads();
    }
    if (tid == 0) {
        float lg[Ee];
#pragma unroll
        for (int e = 0; e < Ee; e++) lg[e] = part[0][e] + br[e];
        float m1 = -3.4e38f, m2 = -3.4e38f;
#pragma unroll
        for (int e = 0; e < Ee; e++) {
            float v = lg[e];
            if (v > m1) { m2 = m1; m1 = v; }
            else if (v > m2) m2 = v;
        }
        float sum = 0.f, we[Ee];
#pragma unroll
        for (int e = 0; e < Ee; e++) {
            we[e] = (lg[e] < m2) ? 0.f : expf(lg[e] - m1);
            sum += we[e];
        }
        float inv = 1.f / sum;
#pragma unroll
        for (int e = 0; e < Ee; e++) wout[(long)t * Ee + e] = we[e] * inv;
#pragma unroll
        for (int e = 0; e < NEXP; e++) {
            if (we[e + 1] != 0.f) {
                int p = atomicAdd(&cnt[e], 1);
                eidx[(long)e * Tt + p] = t;
            }
        }
    }
}

// ---------------- FiLM: inputs as fp16 hi/lo pairs; write ytf hi(/lo) ----------------
__global__ __launch_bounds__(256) void film_kernel(const __half* __restrict__ t0h,
                                                   const __half* __restrict__ t0l,
                                                   const __half* __restrict__ t1h,
                                                   const __half* __restrict__ t1l,
                                                   const float* __restrict__ b0,
                                                   const float* __restrict__ b1,
                                                   __half* __restrict__ hi,
                                                   __half* __restrict__ lo, int wantLo)
{
    long i = (long)blockIdx.x * 256 + threadIdx.x;
    int d = (int)(i & (Dm - 1));
    float t0 = __half2float(t0h[i]) + __half2float(t0l[i]);
    float t1 = __half2float(t1h[i]) + __half2float(t1l[i]);
    float y = gelu_f(t0 + b0[d]) * (t1 + b1[d]);
    __half h = __float2half_rn(y);
    hi[i] = h;
    if (wantLo) lo[i] = __float2half_rn(y - __half2float(h));
}

// ---------------- expert mixing (ytf from hi/lo; PA fp16) ----------------
__global__ __launch_bounds__(256) void mix_kernel(const __half* __restrict__ pe,
                                                  const __half* __restrict__ ae,
                                                  const float* __restrict__ Pb,
                                                  const float* __restrict__ Ab,
                                                  const float* __restrict__ w,
                                                  __half* __restrict__ hi,
                                                  __half* __restrict__ lo, int wantLo)
{
    int t = blockIdx.x;
    __shared__ float ws[Ee];
    if (threadIdx.x < Ee) ws[threadIdx.x] = w[(long)t * Ee + threadIdx.x];
    __syncthreads();
#pragma unroll
    for (int it = 0; it < 4; it++) {
        int d = threadIdx.x + it * 256;
        long td = (long)t * Dm + d;
        float yv = __half2float(hi[td]);
        if (wantLo) yv += __half2float(lo[td]);
        float out = ws[0] * gelu_f(yv);
#pragma unroll
        for (int e = 0; e < NEXP; e++) {
            float we = ws[e + 1];
            if (we != 0.f) {
                float p = __half2float(pe[(long)e * Tt * Dm + td]) + Pb[e * Dm + d];
                float a = __half2float(ae[(long)e * Tt * Dm + td]) + Ab[e * Dm + d];
                out += we * (p * yv + a);
            }
        }
        __half h = __float2half_rn(out);
        hi[td] = h;
        if (wantLo) lo[td] = __float2half_rn(out - __half2float(h));
    }
}

// ---------------- host helpers ----------------
static float* symf(const void* s) { void* p = nullptr; cudaGetSymbolAddress(&p, s); return (float*)p; }
static __half* symh(const void* s) { void* p = nullptr; cudaGetSymbolAddress(&p, s); return (__half*)p; }
static int* symi(const void* s) { void* p = nullptr; cudaGetSymbolAddress(&p, s); return (int*)p; }

static void tgemm(const __half* ahi, const __half* alo,
                  const __half* bhi, const __half* blo,
                  const float* bias, const float* resid,
                  float* C, __half* Chi, __half* Clo,
                  int N, int K, int Z, long sB, long sC, int act, int terms)
{
    dim3 grid(N / BN, Tt / BM, Z);
    mma_gemm_kernel<<<grid, 256, SMEM_MM>>>(ahi, alo, bhi, blo, bias, resid,
                                            C, Chi, Clo, Tt, N, K, sB, sC, act,
                                            bias != nullptr, resid != nullptr,
                                            C != nullptr, Chi != nullptr, Clo != nullptr,
                                            terms);
}

extern "C" void kernel_launch(void* const* d_in, const int* in_sizes, int n_in,
                              void* d_out, int out_size)
{
    const float* x_in  = (const float*)d_in[0];
    const float* ln1_g = (const float*)d_in[1];
    const float* ln1_b = (const float*)d_in[2];
    const float* Wqkv  = (const float*)d_in[3];
    const float* bqkv  = (const float*)d_in[4];
    const float* Wo    = (const float*)d_in[5];
    const float* bo    = (const float*)d_in[6];
    const float* Wr    = (const float*)d_in[7];
    const float* br    = (const float*)d_in[8];
    const float* Wa1   = (const float*)d_in[9];
    const float* ba1   = (const float*)d_in[10];
    const float* Wa2   = (const float*)d_in[11];
    const float* ba2   = (const float*)d_in[12];
    const float* ln2_g = (const float*)d_in[13];
    const float* ln2_b = (const float*)d_in[14];
    const float* Wb0   = (const float*)d_in[15];
    const float* bb0   = (const float*)d_in[16];
    const float* Wb1   = (const float*)d_in[17];
    const float* bb1   = (const float*)d_in[18];
    const float* We_p  = (const float*)d_in[19];
    const float* be_p  = (const float*)d_in[20];
    const float* We_a  = (const float*)d_in[21];
    const float* be_a  = (const float*)d_in[22];

    float* X   = symf(g_x);
    __half* PA = symh(g_pa);
    float* Wt  = symf(g_w);
    __half* WHI = symh(g_whi);
    __half* WLO = symh(g_wlo);
    __half* AHI = symh(g_ahi);
    __half* ALO = symh(g_alo);
    __half* MHI = symh(g_mhi);
    __half* MLO = symh(g_mlo);
    __half* QKVH = symh(g_qkvh);
    __half* VT  = symh(g_vt);
    int* CNT = symi(g_cnt);
    int* EIDX = symi(g_eidx);

    cudaFuncSetAttribute(mma_gemm_kernel,
                         cudaFuncAttributeMaxDynamicSharedMemorySize, SMEM_MM);
    cudaFuncSetAttribute(mma_gather_kernel,
                         cudaFuncAttributeMaxDynamicSharedMemorySize, SMEM_MM);
    cudaFuncSetAttribute(flash_kernel,
                         cudaFuncAttributeMaxDynamicSharedMemorySize, SMEM_F);

    // ---- weight transpose + split (5 launches, 64x128 tiles) ----
    {
        dim3 g1(3072 / 128, 1024 / 64, Lnum);
        wsplit_kernel<<<g1, 256>>>(Wqkv, WHI + OFF_QKV, WLO + OFF_QKV,
                                   1024, 3072, 3072L * 1024, PER_L);
        dim3 g2(8, 16, 6);
        wsplit3_kernel<<<g2, 256>>>(Wo, Wb0, Wb1, WHI, WLO);
        dim3 g3(8, 16, 28);
        wsplitE_kernel<<<g3, 256>>>(We_p, We_a, WHI, WLO);
        dim3 g4(4096 / 128, 1024 / 64, Lnum);
        wsplit_kernel<<<g4, 256>>>(Wa1, WHI + OFF_WA1, WLO + OFF_WA1,
                                   1024, 4096, 4096L * 1024, PER_L);
        dim3 g5(1024 / 128, 4096 / 64, Lnum);
        wsplit_kernel<<<g5, 256>>>(Wa2, WHI + OFF_WA2, WLO + OFF_WA2,
                                   4096, 1024, 4096L * 1024, PER_L);
    }

    cudaMemcpyAsync(X, x_in, (size_t)Tt * Dm * sizeof(float),
                    cudaMemcpyDeviceToDevice, 0);

    for (int l = 0; l < Lnum; l++) {
        const __half* whl = WHI + (long)l * PER_L;
        const __half* wll = WLO + (long)l * PER_L;
        const int tpost = (l == Lnum - 1) ? 2 : 3;
        const int loPost = (tpost == 3) ? 1 : 0;

        // --- attention (QKV 2-term) ---
        ln_split_kernel<<<Tt, 256>>>(X, ln1_g + l * Dm, ln1_b + l * Dm, AHI, ALO, 0);
        tgemm(AHI, ALO, whl + OFF_QKV, wll + OFF_QKV,
              bqkv + (long)l * 3 * INNERd, nullptr,
              nullptr, QKVH, nullptr, 3 * INNERd, Dm, 1, 0, 0, 0, 2);

        {
            dim3 grid(Nn / 32, DHh / 32, Bb * Hh);
            vtrans_kernel<<<grid, 256>>>(QKVH, VT);
        }
        {
            dim3 grid(Nn / 128, Bb * Hh);
            flash_kernel<<<grid, 256, SMEM_F>>>(QKVH, VT, AHI, ALO);
        }
        tgemm(AHI, ALO, whl + OFF_WO, wll + OFF_WO,
              bo + (long)l * Dm, X, X, nullptr, nullptr, Dm, INNERd, 1, 0, 0, 0, 3);

        // --- router + expert gather ---
        reset_cnt_kernel<<<1, 32>>>(CNT);
        router_kernel<<<Tt, 128>>>(X, Wr + (long)l * Dm * Ee, br + (long)l * Ee,
                                   Wt + (long)l * Tt * Ee, CNT, EIDX);

        // --- FiLM trunk: Wb GEMM -> hi/lo (T0 at MHI/MLO[0], T1 at +Tt*Dm) ---
        ln_split_kernel<<<Tt, 256>>>(X, ln2_g + l * Dm, ln2_b + l * Dm, AHI, ALO, loPost);
        tgemm(AHI, ALO, whl + OFF_WB0, wll + OFF_WB0,
              nullptr, nullptr, nullptr, MHI, MLO,
              Dm, Dm, 2, SZ1M, (long)Tt * Dm, 0, tpost);
        film_kernel<<<(Tt * Dm) / 256, 256>>>(MHI, MLO, MHI + (long)Tt * Dm,
                                              MLO + (long)Tt * Dm,
                                              bb0 + (long)l * Dm, bb1 + (long)l * Dm,
                                              AHI, ALO, loPost);

        // --- sparse gathered expert GEMMs (fp16 out) ---
        {
            dim3 grid(Dm / BN, Tt / BM, 2 * NEXP);
            mma_gather_kernel<<<grid, 256, SMEM_MM>>>(
                AHI, ALO, whl + OFF_WEP, wll + OFF_WEP, PA, CNT, EIDX, tpost);
        }

        // --- mix (in-place on AHI/ALO) ---
        mix_kernel<<<Tt, 256>>>(PA, PA + (long)NEXP * Tt * Dm,
                                be_p + (long)l * NEXP * Dm,
                                be_a + (long)l * NEXP * Dm,
                                Wt + (long)l * Tt * Ee, AHI, ALO, loPost);

        // --- adaptor MLP + residual ---
        tgemm(AHI, ALO, whl + OFF_WA1, wll + OFF_WA1,
              ba1 + (long)l * MLPd, nullptr,
              nullptr, MHI, (loPost ? MLO : nullptr), MLPd, Dm, 1, 0, 0, 1, tpost);
        tgemm(MHI, MLO, whl + OFF_WA2, wll + OFF_WA2,
              ba2 + (long)l * Dm, X, X, nullptr, nullptr, Dm, MLPd, 1, 0, 0, 0, tpost);
    }

    // outputs: x [B,N,D] then stacked router weights [L,B,N,E]
    cudaMemcpyAsync(d_out, X, (size_t)Tt * Dm * sizeof(float),
                    cudaMemcpyDeviceToDevice, 0);
    if (out_size >= Tt * Dm + Lnum * Tt * Ee) {
        cudaMemcpyAsync((float*)d_out + (size_t)Tt * Dm, Wt,
                        (size_t)Lnum * Tt * Ee * sizeof(float),
                        cudaMemcpyDeviceToDevice, 0);
    }
}

// round 17
// speedup vs baseline: 1.0057x; 1.0057x over previous
#include <cuda_runtime.h>
#include <cuda_fp16.h>
#include <cstdint>
#include <math.h>

// ---------------- problem constants ----------------
#define Dm     1024
#define Lnum   2
#define Hh     16
#define DHh    64
#define INNERd 1024
#define MLPd   4096
#define Ee     8
#define Bb     4
#define Nn     1024
#define Tt     (Bb*Nn)
#define NEXP   (Ee-1)

// weight pack offsets (elements, per layer)
#define SZ1M   (1024L*1024L)
#define OFF_QKV 0L
#define OFF_WO  (OFF_QKV + 3072L*1024L)
#define OFF_WB0 (OFF_WO  + SZ1M)
#define OFF_WB1 (OFF_WB0 + SZ1M)
#define OFF_WEP (OFF_WB1 + SZ1M)
#define OFF_WEA (OFF_WEP + 7L*SZ1M)
#define OFF_WA1 (OFF_WEA + 7L*SZ1M)
#define OFF_WA2 (OFF_WA1 + 4096L*1024L)
#define PER_L   (OFF_WA2 + 4096L*1024L)

// ---------------- scratch (device globals) ----------------
__device__ float g_x[Tt*Dm];
__device__ __half g_pa[(size_t)2*NEXP*Tt*Dm];
__device__ float g_w[Lnum*Tt*Ee];
__device__ __half g_whi[2L*PER_L];
__device__ __half g_wlo[2L*PER_L];
__device__ __half g_ahi[(size_t)Tt*Dm];
__device__ __half g_alo[(size_t)Tt*Dm];
__device__ __half g_mhi[(size_t)Tt*MLPd];
__device__ __half g_mlo[(size_t)Tt*MLPd];
__device__ __half g_qkvh[(size_t)Tt*3*INNERd];
__device__ __half g_vt[(size_t)Bb*Hh*DHh*Nn];
__device__ int g_cnt[NEXP];
__device__ int g_eidx[(size_t)NEXP*Tt];

__device__ __forceinline__ float gelu_f(float v) {
    return 0.5f * v * (1.0f + erff(v * 0.7071067811865475f));
}

__device__ __forceinline__ uint32_t smem_u32(const void* p) {
    uint32_t a;
    asm("{ .reg .u64 t; cvta.to.shared.u64 t, %1; cvt.u32.u64 %0, t; }"
        : "=r"(a) : "l"(p));
    return a;
}
__device__ __forceinline__ void ldmx4(uint32_t* r, uint32_t addr) {
    asm volatile("ldmatrix.sync.aligned.m8n8.x4.shared.b16 {%0,%1,%2,%3}, [%4];"
        : "=r"(r[0]), "=r"(r[1]), "=r"(r[2]), "=r"(r[3]) : "r"(addr));
}
__device__ __forceinline__ void ldmx2(uint32_t* r, uint32_t addr) {
    asm volatile("ldmatrix.sync.aligned.m8n8.x2.shared.b16 {%0,%1}, [%2];"
        : "=r"(r[0]), "=r"(r[1]) : "r"(addr));
}
__device__ __forceinline__ void mma16816(float* d, const uint32_t* a, const uint32_t* b) {
    asm volatile("mma.sync.aligned.m16n8k16.row.col.f32.f16.f16.f32 "
        "{%0,%1,%2,%3}, {%4,%5,%6,%7}, {%8,%9}, {%0,%1,%2,%3};"
        : "+f"(d[0]), "+f"(d[1]), "+f"(d[2]), "+f"(d[3])
        : "r"(a[0]), "r"(a[1]), "r"(a[2]), "r"(a[3]), "r"(b[0]), "r"(b[1]));
}

// ================= split HMMA GEMM (2 or 3 terms), 2-stage, 2 CTAs/SM =================
#define BM 128
#define BN 128
#define BK 32
#define LDT 40
#define TILE_B (128*LDT*2)
#define ST_AHI 0
#define ST_ALO (1*TILE_B)
#define ST_BHI (2*TILE_B)
#define ST_BLO (3*TILE_B)
#define STAGE_B (4*TILE_B)
#define SMEM_MM (2*STAGE_B)

#define GEMM_PHASE(base, ph)                                                      \
    do {                                                                          \
        uint32_t bhi[4][2], blo[4][2], af[4][4];                                  \
        _Pragma("unroll")                                                         \
        for (int nt = 0; nt < 4; nt++) {                                          \
            int rr = wn * 32 + nt * 8 + (lane & 7);                               \
            uint32_t co = (uint32_t)(rr * LDT + (ph) * 16 + ((lane >> 3) & 1) * 8) * 2; \
            ldmx2(bhi[nt], (base) + ST_BHI + co);                                 \
            ldmx2(blo[nt], (base) + ST_BLO + co);                                 \
        }                                                                         \
        _Pragma("unroll")                                                         \
        for (int mt = 0; mt < 4; mt++) {                                          \
            int rr = wm * 64 + mt * 16 + (lane & 15);                             \
            uint32_t co = (uint32_t)(rr * LDT + (ph) * 16 + (lane >> 4) * 8) * 2; \
            ldmx4(af[mt], (base) + ST_AHI + co);                                  \
        }                                                                         \
        _Pragma("unroll")                                                         \
        for (int mt = 0; mt < 4; mt++)                                            \
            _Pragma("unroll")                                                     \
            for (int nt = 0; nt < 4; nt++) {                                      \
                mma16816(acc[mt][nt], af[mt], bhi[nt]);                           \
                mma16816(acc[mt][nt], af[mt], blo[nt]);                           \
            }                                                                     \
        if (terms == 3) {                                                         \
            _Pragma("unroll")                                                     \
            for (int mt = 0; mt < 4; mt++) {                                      \
                int rr = wm * 64 + mt * 16 + (lane & 15);                         \
                uint32_t co = (uint32_t)(rr * LDT + (ph) * 16 + (lane >> 4) * 8) * 2; \
                ldmx4(af[mt], (base) + ST_ALO + co);                              \
            }                                                                     \
            _Pragma("unroll")                                                     \
            for (int mt = 0; mt < 4; mt++)                                        \
                _Pragma("unroll")                                                 \
                for (int nt = 0; nt < 4; nt++)                                    \
                    mma16816(acc[mt][nt], af[mt], bhi[nt]);                       \
        }                                                                         \
    } while (0)

__global__ __launch_bounds__(256, 2) void mma_gemm_kernel(
    const __half* __restrict__ Ahi, const __half* __restrict__ Alo,
    const __half* __restrict__ Bhi, const __half* __restrict__ Blo,
    const float* __restrict__ bias, const float* __restrict__ resid,
    float* __restrict__ C, __half* __restrict__ Chi, __half* __restrict__ Clo,
    int M, int N, int K, long sB, long sC, int act,
    int hasBias, int hasRes, int wantF32, int wantHi, int wantLo, int terms)
{
    extern __shared__ char smem[];
    uint32_t sb = smem_u32(smem);
    const int tid = threadIdx.x;
    const int wid = tid >> 5;
    const int lane = tid & 31;
    const long z = blockIdx.z;
    Bhi += z * sB;
    Blo += z * sB;
    if (wantF32) C += z * sC;
    if (wantHi) Chi += z * sC;
    if (wantLo) Clo += z * sC;
    const float* res = hasRes ? (resid + z * sC) : nullptr;
    const int row0 = blockIdx.y * BM;
    const int col0 = blockIdx.x * BN;
    const int wm = wid & 1;
    const int wn = wid >> 1;

    float acc[4][4][4];
#pragma unroll
    for (int a = 0; a < 4; a++)
#pragma unroll
        for (int b = 0; b < 4; b++)
#pragma unroll
            for (int c = 0; c < 4; c++) acc[a][b][c] = 0.f;

    const int nc = K / BK;

    auto load_stage = [&](int s, int kt) {
        uint32_t base = sb + s * STAGE_B;
#pragma unroll
        for (int i = 0; i < 8; i++) {
            int idx = i * 256 + tid;
            int mat = idx >> 9;
            if (terms == 2 && mat == 1) continue;
            int rem = idx & 511;
            int r = rem >> 2, c = rem & 3;
            uint32_t sa = base + mat * TILE_B + (uint32_t)(r * LDT + c * 8) * 2;
            const __half* gp;
            if (mat == 0)      gp = Ahi + (long)(row0 + r) * K + kt + c * 8;
            else if (mat == 1) gp = Alo + (long)(row0 + r) * K + kt + c * 8;
            else if (mat == 2) gp = Bhi + (long)(col0 + r) * K + kt + c * 8;
            else               gp = Blo + (long)(col0 + r) * K + kt + c * 8;
            asm volatile("cp.async.cg.shared.global [%0], [%1], 16;"
                         :: "r"(sa), "l"(gp));
        }
        asm volatile("cp.async.commit_group;");
    };

    load_stage(0, 0);

    for (int c = 0; c < nc; c++) {
        int s = c & 1;
        if (c + 1 < nc) {
            load_stage(s ^ 1, (c + 1) * BK);
            asm volatile("cp.async.wait_group 1;");
        } else {
            asm volatile("cp.async.wait_group 0;");
        }
        __syncthreads();
        uint32_t base = sb + s * STAGE_B;
        GEMM_PHASE(base, 0);
        GEMM_PHASE(base, 1);
        __syncthreads();
    }

#pragma unroll
    for (int mt = 0; mt < 4; mt++) {
#pragma unroll
        for (int nt = 0; nt < 4; nt++) {
            int rb = row0 + wm * 64 + mt * 16 + (lane >> 2);
            int cc = col0 + wn * 32 + nt * 8 + (lane & 3) * 2;
            float b0 = 0.f, b1 = 0.f;
            if (hasBias) { b0 = bias[cc]; b1 = bias[cc + 1]; }
#pragma unroll
            for (int hf = 0; hf < 2; hf++) {
                int rr = rb + hf * 8;
                float v0 = acc[mt][nt][hf * 2] + b0;
                float v1 = acc[mt][nt][hf * 2 + 1] + b1;
                if (act == 1) { v0 = gelu_f(v0); v1 = gelu_f(v1); }
                if (hasRes) {
                    v0 += res[(long)rr * N + cc];
                    v1 += res[(long)rr * N + cc + 1];
                }
                long o = (long)rr * N + cc;
                if (wantF32) *(float2*)&C[o] = make_float2(v0, v1);
                if (wantHi) {
                    __half h0 = __float2half_rn(v0), h1 = __float2half_rn(v1);
                    *(__half2*)&Chi[o] = __halves2half2(h0, h1);
                    if (wantLo) {
                        __half l0 = __float2half_rn(v0 - __half2float(h0));
                        __half l1 = __float2half_rn(v1 - __half2float(h1));
                        *(__half2*)&Clo[o] = __halves2half2(l0, l1);
                    }
                }
            }
        }
    }
}

// ================= token-gathered sparse expert GEMM (fp16 output) =================
__global__ __launch_bounds__(256, 2) void mma_gather_kernel(
    const __half* __restrict__ Ahi, const __half* __restrict__ Alo,
    const __half* __restrict__ Whi, const __half* __restrict__ Wlo,
    __half* __restrict__ PA,
    const int* __restrict__ cnt, const int* __restrict__ eidx, int terms)
{
    const int z = blockIdx.z;
    const int e = z % NEXP;
    const int n = cnt[e];
    const int row0 = blockIdx.y * BM;
    if (row0 >= n) return;

    extern __shared__ char smem[];
    uint32_t sb = smem_u32(smem);
    __shared__ int sidx[BM];
    const int tid = threadIdx.x;
    const int wid = tid >> 5;
    const int lane = tid & 31;
    const __half* Bhi = Whi + (long)z * SZ1M;
    const __half* Blo = Wlo + (long)z * SZ1M;
    __half* C = PA + (long)z * Tt * Dm;
    const int col0 = blockIdx.x * BN;
    const int wm = wid & 1;
    const int wn = wid >> 1;
    const int K = Dm;

    if (tid < BM) {
        int rr = row0 + tid;
        sidx[tid] = eidx[(long)e * Tt + (rr < n ? rr : n - 1)];
    }
    __syncthreads();

    float acc[4][4][4];
#pragma unroll
    for (int a = 0; a < 4; a++)
#pragma unroll
        for (int b = 0; b < 4; b++)
#pragma unroll
            for (int c = 0; c < 4; c++) acc[a][b][c] = 0.f;

    const int nc = K / BK;

    auto load_stage = [&](int s, int kt) {
        uint32_t base = sb + s * STAGE_B;
#pragma unroll
        for (int i = 0; i < 8; i++) {
            int idx = i * 256 + tid;
            int mat = idx >> 9;
            if (terms == 2 && mat == 1) continue;
            int rem = idx & 511;
            int r = rem >> 2, c = rem & 3;
            uint32_t sa = base + mat * TILE_B + (uint32_t)(r * LDT + c * 8) * 2;
            const __half* gp;
            if (mat == 0)      gp = Ahi + (long)sidx[r] * K + kt + c * 8;
            else if (mat == 1) gp = Alo + (long)sidx[r] * K + kt + c * 8;
            else if (mat == 2) gp = Bhi + (long)(col0 + r) * K + kt + c * 8;
            else               gp = Blo + (long)(col0 + r) * K + kt + c * 8;
            asm volatile("cp.async.cg.shared.global [%0], [%1], 16;"
                         :: "r"(sa), "l"(gp));
        }
        asm volatile("cp.async.commit_group;");
    };

    load_stage(0, 0);

    for (int c = 0; c < nc; c++) {
        int s = c & 1;
        if (c + 1 < nc) {
            load_stage(s ^ 1, (c + 1) * BK);
            asm volatile("cp.async.wait_group 1;");
        } else {
            asm volatile("cp.async.wait_group 0;");
        }
        __syncthreads();
        uint32_t base = sb + s * STAGE_B;
        GEMM_PHASE(base, 0);
        GEMM_PHASE(base, 1);
        __syncthreads();
    }

#pragma unroll
    for (int mt = 0; mt < 4; mt++) {
#pragma unroll
        for (int nt = 0; nt < 4; nt++) {
            int lr = wm * 64 + mt * 16 + (lane >> 2);
            int cc = col0 + wn * 32 + nt * 8 + (lane & 3) * 2;
#pragma unroll
            for (int hf = 0; hf < 2; hf++) {
                int lrr = lr + hf * 8;
                if (row0 + lrr < n) {
                    long o = (long)sidx[lrr] * Dm + cc;
                    *(__half2*)&C[o] = __halves2half2(
                        __float2half_rn(acc[mt][nt][hf * 2]),
                        __float2half_rn(acc[mt][nt][hf * 2 + 1]));
                }
            }
        }
    }
}

// ================= fused flash attention =================
#define FLD 72
#define F_QOFF 0
#define F_SOFF (128*FLD*2)
#define F_KOFF (2*128*FLD*2)
#define F_KT  (64*FLD*2)
#define F_VOFF (F_KOFF + 2*F_KT)
#define SMEM_F (F_VOFF + 2*F_KT)

__global__ __launch_bounds__(256, 2) void flash_kernel(
    const __half* __restrict__ qkvh, const __half* __restrict__ vt,
    __half* __restrict__ Ohi, __half* __restrict__ Olo)
{
    extern __shared__ char smem[];
    __shared__ float rs[128][2];
    uint32_t sb = smem_u32(smem);
    const int tid = threadIdx.x;
    const int wid = tid >> 5;
    const int lane = tid & 31;
    const int z = blockIdx.y;
    const int b = z >> 4, h = z & 15;
    const int row0 = blockIdx.x * 128;
    const int wm = wid & 1;
    const int wn = wid >> 1;

    const __half* Qg = qkvh + (long)(b * Nn) * 3072 + h * 64;
    const __half* Kg = Qg + INNERd;
    const __half* Vg = vt + (long)z * DHh * Nn;

#pragma unroll
    for (int i = 0; i < 4; i++) {
        int idx = i * 256 + tid;
        int r = idx >> 3, c = idx & 7;
        uint32_t sa = sb + F_QOFF + (uint32_t)(r * FLD + c * 8) * 2;
        const __half* gp = Qg + (long)(row0 + r) * 3072 + c * 8;
        asm volatile("cp.async.cg.shared.global [%0], [%1], 16;"
                     :: "r"(sa), "l"(gp));
    }
    asm volatile("cp.async.commit_group;");

    auto load_kv = [&](int s, int kt) {
#pragma unroll
        for (int i = 0; i < 2; i++) {
            int idx = i * 256 + tid;
            int r = idx >> 3, c = idx & 7;
            uint32_t sa = sb + F_KOFF + s * F_KT + (uint32_t)(r * FLD + c * 8) * 2;
            const __half* gp = Kg + (long)(kt + r) * 3072 + c * 8;
            asm volatile("cp.async.cg.shared.global [%0], [%1], 16;"
                         :: "r"(sa), "l"(gp));
        }
#pragma unroll
        for (int i = 0; i < 2; i++) {
            int idx = i * 256 + tid;
            int r = idx >> 3, c = idx & 7;
            uint32_t sa = sb + F_VOFF + s * F_KT + (uint32_t)(r * FLD + c * 8) * 2;
            const __half* gp = Vg + (long)r * Nn + kt + c * 8;
            asm volatile("cp.async.cg.shared.global [%0], [%1], 16;"
                         :: "r"(sa), "l"(gp));
        }
        asm volatile("cp.async.commit_group;");
    };

    load_kv(0, 0);
    asm volatile("cp.async.wait_group 0;");
    __syncthreads();

    float oacc[4][2][4];
#pragma unroll
    for (int a = 0; a < 4; a++)
#pragma unroll
        for (int bb = 0; bb < 2; bb++)
#pragma unroll
            for (int c = 0; c < 4; c++) oacc[a][bb][c] = 0.f;
    float fsum = 0.f;

    const int nt_tiles = Nn / 64;
    for (int t = 0; t < nt_tiles; t++) {
        int s = t & 1;
        if (t + 1 < nt_tiles) load_kv(s ^ 1, (t + 1) * 64);

        float sacc[4][2][4];
#pragma unroll
        for (int a = 0; a < 4; a++)
#pragma unroll
            for (int bb = 0; bb < 2; bb++)
#pragma unroll
                for (int c = 0; c < 4; c++) sacc[a][bb][c] = 0.f;
#pragma unroll
        for (int ph = 0; ph < 4; ph++) {
            uint32_t af[4][4], bf[2][2];
#pragma unroll
            for (int mt = 0; mt < 4; mt++) {
                int rr = wm * 64 + mt * 16 + (lane & 15);
                uint32_t co = (uint32_t)(rr * FLD + ph * 16 + (lane >> 4) * 8) * 2;
                ldmx4(af[mt], sb + F_QOFF + co);
            }
#pragma unroll
            for (int nt = 0; nt < 2; nt++) {
                int rr = wn * 16 + nt * 8 + (lane & 7);
                uint32_t co = (uint32_t)(rr * FLD + ph * 16 + ((lane >> 3) & 1) * 8) * 2;
                ldmx2(bf[nt], sb + F_KOFF + s * F_KT + co);
            }
#pragma unroll
            for (int mt = 0; mt < 4; mt++)
#pragma unroll
                for (int nt = 0; nt < 2; nt++)
                    mma16816(sacc[mt][nt], af[mt], bf[nt]);
        }
#pragma unroll
        for (int mt = 0; mt < 4; mt++)
#pragma unroll
            for (int nt = 0; nt < 2; nt++)
#pragma unroll
                for (int hf = 0; hf < 2; hf++) {
                    int row = wm * 64 + mt * 16 + (lane >> 2) + hf * 8;
                    int col = wn * 16 + nt * 8 + (lane & 3) * 2;
                    float v0 = expf(sacc[mt][nt][hf * 2] * 0.125f);
                    float v1 = expf(sacc[mt][nt][hf * 2 + 1] * 0.125f);
                    *(__half2*)(smem + F_SOFF + (size_t)(row * FLD + col) * 2) =
                        __halves2half2(__float2half_rn(v0), __float2half_rn(v1));
                }
        __syncthreads();

        {
            int r = tid & 127, hf2 = tid >> 7;
            const __half2* ap = (const __half2*)(smem + F_SOFF
                                                 + (size_t)(r * FLD + hf2 * 32) * 2);
            float lsum = 0.f;
#pragma unroll
            for (int j = 0; j < 16; j++) {
                float2 f = __half22float2(ap[j]);
                lsum += f.x + f.y;
            }
            fsum += lsum;
        }

#pragma unroll
        for (int ph = 0; ph < 4; ph++) {
            uint32_t af[4][4], bf[2][2];
#pragma unroll
            for (int mt = 0; mt < 4; mt++) {
                int rr = wm * 64 + mt * 16 + (lane & 15);
                uint32_t co = (uint32_t)(rr * FLD + ph * 16 + (lane >> 4) * 8) * 2;
                ldmx4(af[mt], sb + F_SOFF + co);
            }
#pragma unroll
            for (int nt = 0; nt < 2; nt++) {
                int rr = wn * 16 + nt * 8 + (lane & 7);
                uint32_t co = (uint32_t)(rr * FLD + ph * 16 + ((lane >> 3) & 1) * 8) * 2;
                ldmx2(bf[nt], sb + F_VOFF + s * F_KT + co);
            }
#pragma unroll
            for (int mt = 0; mt < 4; mt++)
#pragma unroll
                for (int nt = 0; nt < 2; nt++)
                    mma16816(oacc[mt][nt], af[mt], bf[nt]);
        }
        asm volatile("cp.async.wait_group 0;");
        __syncthreads();
    }

    rs[tid & 127][tid >> 7] = fsum;
    __syncthreads();

#pragma unroll
    for (int mt = 0; mt < 4; mt++)
#pragma unroll
        for (int nt = 0; nt < 2; nt++)
#pragma unroll
            for (int hf = 0; hf < 2; hf++) {
                int lr = wm * 64 + mt * 16 + (lane >> 2) + hf * 8;
                int cc = wn * 16 + nt * 8 + (lane & 3) * 2;
                float inv = 1.f / (rs[lr][0] + rs[lr][1]);
                float v0 = oacc[mt][nt][hf * 2] * inv;
                float v1 = oacc[mt][nt][hf * 2 + 1] * inv;
                long o = (long)(b * Nn + row0 + lr) * INNERd + h * 64 + cc;
                __half h0 = __float2half_rn(v0), h1 = __float2half_rn(v1);
                *(__half2*)&Ohi[o] = __halves2half2(h0, h1);
                __half l0 = __float2half_rn(v0 - __half2float(h0));
                __half l1 = __float2half_rn(v1 - __half2float(h1));
                *(__half2*)&Olo[o] = __halves2half2(l0, l1);
            }
}

// ---------------- V transpose ----------------
__global__ __launch_bounds__(256) void vtrans_kernel(const __half* __restrict__ qkvh,
                                                     __half* __restrict__ vt)
{
    __shared__ __half t[32][33];
    int z = blockIdx.z, b = z >> 4, h = z & 15;
    int k0 = blockIdx.x * 32, d0 = blockIdx.y * 32;
    int tx = threadIdx.x & 31, ty = threadIdx.x >> 5;
#pragma unroll
    for (int i = 0; i < 4; i++) {
        int k = k0 + ty + i * 8;
        t[ty + i * 8][tx] = qkvh[(long)(b * Nn + k) * 3072 + 2048 + h * 64 + d0 + tx];
    }
    __syncthreads();
#pragma unroll
    for (int i = 0; i < 4; i++) {
        int d = d0 + ty + i * 8;
        vt[((long)z * 64 + d) * Nn + k0 + tx] = t[tx][ty + i * 8];
    }
}

// ---------------- weight transpose + fp16 split core (64x64) ----------------
__device__ __forceinline__ void wsplit_tile(const float* __restrict__ Wz,
                                            __half* __restrict__ hi,
                                            __half* __restrict__ lo,
                                            long ob, int K, int N,
                                            int k0, int n0, int tid)
{
    __shared__ float tile[64][65];
#pragma unroll
    for (int i = 0; i < 4; i++) {
        int idx = i * 256 + tid;
        int r = idx >> 4, c4 = idx & 15;
        float4 v = *(const float4*)(Wz + (long)(k0 + r) * N + n0 + c4 * 4);
        tile[r][c4 * 4 + 0] = v.x; tile[r][c4 * 4 + 1] = v.y;
        tile[r][c4 * 4 + 2] = v.z; tile[r][c4 * 4 + 3] = v.w;
    }
    __syncthreads();
#pragma unroll
    for (int i = 0; i < 2; i++) {
        int idx = i * 256 + tid;
        int nn = idx >> 3, kg = idx & 7;
        __half hbuf[8], lbuf[8];
#pragma unroll
        for (int j = 0; j < 8; j++) {
            float v = tile[kg * 8 + j][nn];
            __half h = __float2half_rn(v);
            hbuf[j] = h;
            lbuf[j] = __float2half_rn(v - __half2float(h));
        }
        long o = ob + (long)(n0 + nn) * K + k0 + kg * 8;
        *(uint4*)(hi + o) = *(uint4*)hbuf;
        *(uint4*)(lo + o) = *(uint4*)lbuf;
    }
}

__global__ __launch_bounds__(256) void wsplit_kernel(
    const float* __restrict__ W, __half* __restrict__ hi, __half* __restrict__ lo,
    int K, int N, long inStride, long outStride)
{
    wsplit_tile(W + blockIdx.z * inStride, hi, lo, (long)blockIdx.z * outStride,
                K, N, blockIdx.y * 64, blockIdx.x * 64, threadIdx.x);
}

__global__ __launch_bounds__(256) void wsplit3_kernel(
    const float* __restrict__ W0, const float* __restrict__ W1,
    const float* __restrict__ W2,
    __half* __restrict__ hi, __half* __restrict__ lo)
{
    int z = blockIdx.z;
    int t = z >> 1, l = z & 1;
    const float* src = (t == 0 ? W0 : (t == 1 ? W1 : W2)) + (long)l * SZ1M;
    long off = (t == 0 ? OFF_WO : (t == 1 ? OFF_WB0 : OFF_WB1)) + (long)l * PER_L;
    wsplit_tile(src, hi, lo, off, 1024, 1024,
                blockIdx.y * 64, blockIdx.x * 64, threadIdx.x);
}

__global__ __launch_bounds__(256) void wsplitE_kernel(
    const float* __restrict__ Wp, const float* __restrict__ Wa,
    __half* __restrict__ hi, __half* __restrict__ lo)
{
    int z = blockIdx.z;
    int l = z / 14, s = z % 14;
    const float* src = (s < 7 ? Wp + (long)l * 7 * SZ1M + (long)s * SZ1M
                              : Wa + (long)l * 7 * SZ1M + (long)(s - 7) * SZ1M);
    long off = (long)l * PER_L + OFF_WEP + (long)s * SZ1M;
    wsplit_tile(src, hi, lo, off, 1024, 1024,
                blockIdx.y * 64, blockIdx.x * 64, threadIdx.x);
}

// ---------------- LayerNorm -> fp16 hi(/lo) ----------------
__global__ __launch_bounds__(256) void ln_split_kernel(
    const float* __restrict__ x, const float* __restrict__ g,
    const float* __restrict__ bta,
    __half* __restrict__ hi, __half* __restrict__ lo, int wantLo)
{
    int t = blockIdx.x, tid = threadIdx.x;
    const float* xp = x + (long)t * Dm;
    __shared__ float r1[256], r2[256];

    float v[4], s = 0.f, s2 = 0.f;
#pragma unroll
    for (int i = 0; i < 4; i++) { v[i] = xp[tid + i * 256]; s += v[i]; s2 += v[i] * v[i]; }
    r1[tid] = s; r2[tid] = s2; __syncthreads();
    for (int st = 128; st > 0; st >>= 1) {
        if (tid < st) { r1[tid] += r1[tid + st]; r2[tid] += r2[tid + st]; }
        __syncthreads();
    }
    float mean = r1[0] * (1.f / Dm);
    float var = r2[0] * (1.f / Dm) - mean * mean;
    float rstd = rsqrtf(var + 1e-5f);
#pragma unroll
    for (int i = 0; i < 4; i++) {
        int d = tid + i * 256;
        float y = (v[i] - mean) * rstd * g[d] + bta[d];
        __half h = __float2half_rn(y);
        hi[(long)t * Dm + d] = h;
        if (wantLo) lo[(long)t * Dm + d] = __float2half_rn(y - __half2float(h));
    }
}

// ---------------- reset expert counters ----------------
__global__ void reset_cnt_kernel(int* cnt)
{
    if (threadIdx.x < NEXP) cnt[threadIdx.x] = 0;
}

// ---------------- router (+ expert token gather) ----------------
__global__ __launch_bounds__(128) void router_kernel(const float* __restrict__ x,
                                                     const float* __restrict__ Wr,
                                                     const float* __restrict__ br,
                                                     float* __restrict__ wout,
                                                     int* __restrict__ cnt,
                                                     int* __restrict__ eidx)
{
    int t = blockIdx.x, tid = threadIdx.x;
    __shared__ float part[128][Ee];
    float acc[Ee];
#pragma unroll
    for (int e = 0; e < Ee; e++) acc[e] = 0.f;
    const float* xp = x + (long)t * Dm;
    for (int d = tid; d < Dm; d += 128) {
        float xv = xp[d];
        const float* wrow = Wr + (long)d * Ee;
#pragma unroll
        for (int e = 0; e < Ee; e++) acc[e] += xv * wrow[e];
    }
#pragma unroll
    for (int e = 0; e < Ee; e++) part[tid][e] = acc[e];
    __syncthreads();
    for (int st = 64; st > 0; st >>= 1) {
        if (tid < st)
#pragma unroll
            for (int e = 0; e < Ee; e++) part[tid][e] += part[tid + st][e];
        __syncthreads();
    }
    if (tid == 0) {
        float lg[Ee];
#pragma unroll
        for (int e = 0; e < Ee; e++) lg[e] = part[0][e] + br[e];
        float m1 = -3.4e38f, m2 = -3.4e38f;
#pragma unroll
        for (int e = 0; e < Ee; e++) {
            float v = lg[e];
            if (v > m1) { m2 = m1; m1 = v; }
            else if (v > m2) m2 = v;
        }
        float sum = 0.f, we[Ee];
#pragma unroll
        for (int e = 0; e < Ee; e++) {
            we[e] = (lg[e] < m2) ? 0.f : expf(lg[e] - m1);
            sum += we[e];
        }
        float inv = 1.f / sum;
#pragma unroll
        for (int e = 0; e < Ee; e++) wout[(long)t * Ee + e] = we[e] * inv;
#pragma unroll
        for (int e = 0; e < NEXP; e++) {
            if (we[e + 1] != 0.f) {
                int p = atomicAdd(&cnt[e], 1);
                eidx[(long)e * Tt + p] = t;
            }
        }
    }
}

// ---------------- FiLM: inputs as fp16 hi/lo pairs; write ytf hi(/lo) ----------------
__global__ __launch_bounds__(256) void film_kernel(const __half* __restrict__ t0h,
                                                   const __half* __restrict__ t0l,
                                                   const __half* __restrict__ t1h,
                                                   const __half* __restrict__ t1l,
                                                   const float* __restrict__ b0,
                                                   const float* __restrict__ b1,
                                                   __half* __restrict__ hi,
                                                   __half* __restrict__ lo, int wantLo)
{
    long i = (long)blockIdx.x * 256 + threadIdx.x;
    int d = (int)(i & (Dm - 1));
    float t0 = __half2float(t0h[i]) + __half2float(t0l[i]);
    float t1 = __half2float(t1h[i]) + __half2float(t1l[i]);
    float y = gelu_f(t0 + b0[d]) * (t1 + b1[d]);
    __half h = __float2half_rn(y);
    hi[i] = h;
    if (wantLo) lo[i] = __float2half_rn(y - __half2float(h));
}

// ---------------- expert mixing (ytf from hi/lo; PA fp16) ----------------
__global__ __launch_bounds__(256) void mix_kernel(const __half* __restrict__ pe,
                                                  const __half* __restrict__ ae,
                                                  const float* __restrict__ Pb,
                                                  const float* __restrict__ Ab,
                                                  const float* __restrict__ w,
                                                  __half* __restrict__ hi,
                                                  __half* __restrict__ lo, int wantLo)
{
    int t = blockIdx.x;
    __shared__ float ws[Ee];
    if (threadIdx.x < Ee) ws[threadIdx.x] = w[(long)t * Ee + threadIdx.x];
    __syncthreads();
#pragma unroll
    for (int it = 0; it < 4; it++) {
        int d = threadIdx.x + it * 256;
        long td = (long)t * Dm + d;
        float yv = __half2float(hi[td]);
        if (wantLo) yv += __half2float(lo[td]);
        float out = ws[0] * gelu_f(yv);
#pragma unroll
        for (int e = 0; e < NEXP; e++) {
            float we = ws[e + 1];
            if (we != 0.f) {
                float p = __half2float(pe[(long)e * Tt * Dm + td]) + Pb[e * Dm + d];
                float a = __half2float(ae[(long)e * Tt * Dm + td]) + Ab[e * Dm + d];
                out += we * (p * yv + a);
            }
        }
        __half h = __float2half_rn(out);
        hi[td] = h;
        if (wantLo) lo[td] = __float2half_rn(out - __half2float(h));
    }
}

// ---------------- host helpers ----------------
static float* symf(const void* s) { void* p = nullptr; cudaGetSymbolAddress(&p, s); return (float*)p; }
static __half* symh(const void* s) { void* p = nullptr; cudaGetSymbolAddress(&p, s); return (__half*)p; }
static int* symi(const void* s) { void* p = nullptr; cudaGetSymbolAddress(&p, s); return (int*)p; }

static void tgemm(const __half* ahi, const __half* alo,
                  const __half* bhi, const __half* blo,
                  const float* bias, const float* resid,
                  float* C, __half* Chi, __half* Clo,
                  int N, int K, int Z, long sB, long sC, int act, int terms)
{
    dim3 grid(N / BN, Tt / BM, Z);
    mma_gemm_kernel<<<grid, 256, SMEM_MM>>>(ahi, alo, bhi, blo, bias, resid,
                                            C, Chi, Clo, Tt, N, K, sB, sC, act,
                                            bias != nullptr, resid != nullptr,
                                            C != nullptr, Chi != nullptr, Clo != nullptr,
                                            terms);
}

extern "C" void kernel_launch(void* const* d_in, const int* in_sizes, int n_in,
                              void* d_out, int out_size)
{
    const float* x_in  = (const float*)d_in[0];
    const float* ln1_g = (const float*)d_in[1];
    const float* ln1_b = (const float*)d_in[2];
    const float* Wqkv  = (const float*)d_in[3];
    const float* bqkv  = (const float*)d_in[4];
    const float* Wo    = (const float*)d_in[5];
    const float* bo    = (const float*)d_in[6];
    const float* Wr    = (const float*)d_in[7];
    const float* br    = (const float*)d_in[8];
    const float* Wa1   = (const float*)d_in[9];
    const float* ba1   = (const float*)d_in[10];
    const float* Wa2   = (const float*)d_in[11];
    const float* ba2   = (const float*)d_in[12];
    const float* ln2_g = (const float*)d_in[13];
    const float* ln2_b = (const float*)d_in[14];
    const float* Wb0   = (const float*)d_in[15];
    const float* bb0   = (const float*)d_in[16];
    const float* Wb1   = (const float*)d_in[17];
    const float* bb1   = (const float*)d_in[18];
    const float* We_p  = (const float*)d_in[19];
    const float* be_p  = (const float*)d_in[20];
    const float* We_a  = (const float*)d_in[21];
    const float* be_a  = (const float*)d_in[22];

    float* X   = symf(g_x);
    __half* PA = symh(g_pa);
    float* Wt  = symf(g_w);
    __half* WHI = symh(g_whi);
    __half* WLO = symh(g_wlo);
    __half* AHI = symh(g_ahi);
    __half* ALO = symh(g_alo);
    __half* MHI = symh(g_mhi);
    __half* MLO = symh(g_mlo);
    __half* QKVH = symh(g_qkvh);
    __half* VT  = symh(g_vt);
    int* CNT = symi(g_cnt);
    int* EIDX = symi(g_eidx);

    cudaFuncSetAttribute(mma_gemm_kernel,
                         cudaFuncAttributeMaxDynamicSharedMemorySize, SMEM_MM);
    cudaFuncSetAttribute(mma_gather_kernel,
                         cudaFuncAttributeMaxDynamicSharedMemorySize, SMEM_MM);
    cudaFuncSetAttribute(flash_kernel,
                         cudaFuncAttributeMaxDynamicSharedMemorySize, SMEM_F);

    // ---- weight transpose + split (5 launches, 64x64 tiles) ----
    {
        dim3 g1(3072 / 64, 1024 / 64, Lnum);
        wsplit_kernel<<<g1, 256>>>(Wqkv, WHI + OFF_QKV, WLO + OFF_QKV,
                                   1024, 3072, 3072L * 1024, PER_L);
        dim3 g2(16, 16, 6);
        wsplit3_kernel<<<g2, 256>>>(Wo, Wb0, Wb1, WHI, WLO);
        dim3 g3(16, 16, 28);
        wsplitE_kernel<<<g3, 256>>>(We_p, We_a, WHI, WLO);
        dim3 g4(4096 / 64, 1024 / 64, Lnum);
        wsplit_kernel<<<g4, 256>>>(Wa1, WHI + OFF_WA1, WLO + OFF_WA1,
                                   1024, 4096, 4096L * 1024, PER_L);
        dim3 g5(1024 / 64, 4096 / 64, Lnum);
        wsplit_kernel<<<g5, 256>>>(Wa2, WHI + OFF_WA2, WLO + OFF_WA2,
                                   4096, 1024, 4096L * 1024, PER_L);
    }

    cudaMemcpyAsync(X, x_in, (size_t)Tt * Dm * sizeof(float),
                    cudaMemcpyDeviceToDevice, 0);

    for (int l = 0; l < Lnum; l++) {
        const __half* whl = WHI + (long)l * PER_L;
        const __half* wll = WLO + (long)l * PER_L;
        const int tpost = (l == Lnum - 1) ? 2 : 3;
        const int loPost = (tpost == 3) ? 1 : 0;

        // --- attention (QKV 2-term) ---
        ln_split_kernel<<<Tt, 256>>>(X, ln1_g + l * Dm, ln1_b + l * Dm, AHI, ALO, 0);
        tgemm(AHI, ALO, whl + OFF_QKV, wll + OFF_QKV,
              bqkv + (long)l * 3 * INNERd, nullptr,
              nullptr, QKVH, nullptr, 3 * INNERd, Dm, 1, 0, 0, 0, 2);

        {
            dim3 grid(Nn / 32, DHh / 32, Bb * Hh);
            vtrans_kernel<<<grid, 256>>>(QKVH, VT);
        }
        {
            dim3 grid(Nn / 128, Bb * Hh);
            flash_kernel<<<grid, 256, SMEM_F>>>(QKVH, VT, AHI, ALO);
        }
        tgemm(AHI, ALO, whl + OFF_WO, wll + OFF_WO,
              bo + (long)l * Dm, X, X, nullptr, nullptr, Dm, INNERd, 1, 0, 0, 0, 3);

        // --- router + expert gather ---
        reset_cnt_kernel<<<1, 32>>>(CNT);
        router_kernel<<<Tt, 128>>>(X, Wr + (long)l * Dm * Ee, br + (long)l * Ee,
                                   Wt + (long)l * Tt * Ee, CNT, EIDX);

        // --- FiLM trunk: Wb GEMM -> hi/lo (T0 at MHI/MLO[0], T1 at +Tt*Dm) ---
        ln_split_kernel<<<Tt, 256>>>(X, ln2_g + l * Dm, ln2_b + l * Dm, AHI, ALO, loPost);
        tgemm(AHI, ALO, whl + OFF_WB0, wll + OFF_WB0,
              nullptr, nullptr, nullptr, MHI, MLO,
              Dm, Dm, 2, SZ1M, (long)Tt * Dm, 0, tpost);
        film_kernel<<<(Tt * Dm) / 256, 256>>>(MHI, MLO, MHI + (long)Tt * Dm,
                                              MLO + (long)Tt * Dm,
                                              bb0 + (long)l * Dm, bb1 + (long)l * Dm,
                                              AHI, ALO, loPost);

        // --- sparse gathered expert GEMMs (fp16 out) ---
        {
            dim3 grid(Dm / BN, Tt / BM, 2 * NEXP);
            mma_gather_kernel<<<grid, 256, SMEM_MM>>>(
                AHI, ALO, whl + OFF_WEP, wll + OFF_WEP, PA, CNT, EIDX, tpost);
        }

        // --- mix (in-place on AHI/ALO) ---
        mix_kernel<<<Tt, 256>>>(PA, PA + (long)NEXP * Tt * Dm,
                                be_p + (long)l * NEXP * Dm,
                                be_a + (long)l * NEXP * Dm,
                                Wt + (long)l * Tt * Ee, AHI, ALO, loPost);

        // --- adaptor MLP + residual ---
        tgemm(AHI, ALO, whl + OFF_WA1, wll + OFF_WA1,
              ba1 + (long)l * MLPd, nullptr,
              nullptr, MHI, (loPost ? MLO : nullptr), MLPd, Dm, 1, 0, 0, 1, tpost);
        tgemm(MHI, MLO, whl + OFF_WA2, wll + OFF_WA2,
              ba2 + (long)l * Dm, X, X, nullptr, nullptr, Dm, MLPd, 1, 0, 0, 0, tpost);
    }

    // outputs: x [B,N,D] then stacked router weights [L,B,N,E]
    cudaMemcpyAsync(d_out, X, (size_t)Tt * Dm * sizeof(float),
                    cudaMemcpyDeviceToDevice, 0);
    if (out_size >= Tt * Dm + Lnum * Tt * Ee) {
        cudaMemcpyAsync((float*)d_out + (size_t)Tt * Dm, Wt,
                        (size_t)Lnum * Tt * Ee * sizeof(float),
                        cudaMemcpyDeviceToDevice, 0);
    }
}